// round 1
// baseline (speedup 1.0000x reference)
#include <cuda_runtime.h>
#include <math.h>
#include <stdint.h>

// ---------------------------------------------------------------------------
// Problem constants
//   B=4, SEQ=1024, DIM=1024, HEADS=16, HD=64, N_EXP=2, SLOTS=512, HID=4096
// Output: [ y : 4*1024*1024 f32 ][ attn : 4*1024*1024*16 f32 ]
// ---------------------------------------------------------------------------

#define OFF_Q       0LL
#define OFF_KV      4194304LL
#define OFF_TMP     12582912LL     // attn scratch (b,h,n,m) 64M floats
#define OFF_ATTOUT  79691776LL
#define OFF_PROJ    83886080LL
#define OFF_X1      88080384LL
#define OFF_LOGITS  92274688LL
#define OFF_DISPT   96468992LL
#define OFF_COMB    100663296LL
#define OFF_SLOTS   104857600LL
#define OFF_H       109051904LL    // 16M floats
#define OFF_YMOE    125829120LL
#define OFF_MOE     130023424LL
#define OFF_RM      134217728LL
#define OFF_RL      134283264LL
#define ARENA_FLOATS 134348800LL

__device__ float g_arena[ARENA_FLOATS];

// ---------------------------------------------------------------------------
// Generic batched SGEMM: C = A(MxK) @ B(KxN) [+bias] [gelu]
// Row-major, all of M,N multiples of 128, K multiple of 8.
// batch z: A += z*sA, B += (z % nBmod)*sB (nBmod==0 -> z), bias likewise, C += z*sC
// act: 0 = none, 1 = +bias, 2 = +bias then gelu(tanh approx)
// ---------------------------------------------------------------------------
__device__ __forceinline__ float gelu_tanh(float v) {
    const float c0 = 0.7978845608028654f;   // sqrt(2/pi)
    float t = tanhf(c0 * (v + 0.044715f * v * v * v));
    return 0.5f * v * (1.0f + t);
}

__global__ void sgemm(const float* __restrict__ A, const float* __restrict__ Bm,
                      const float* __restrict__ bias, float* __restrict__ C,
                      int M, int N, int K,
                      long long sA, long long sB, long long sBias, long long sC,
                      int nBmod, int act)
{
    int z = blockIdx.z;
    int zb = nBmod ? (z % nBmod) : z;
    A  += (long long)z * sA;
    Bm += (long long)zb * sB;
    if (act >= 1) bias += (long long)zb * sBias;
    C  += (long long)z * sC;

    __shared__ float As[8][128];   // [k][m] transposed
    __shared__ float Bs[8][128];   // [k][n]

    int bx = blockIdx.x, by = blockIdx.y;
    int tid = threadIdx.x;
    int tx = tid & 15, ty = tid >> 4;

    int aRow = tid >> 1;
    int aCol = (tid & 1) * 4;
    int bRow = tid >> 5;
    int bCol = (tid & 31) * 4;

    const float* Aptr = A + (long long)(by * 128 + aRow) * K + aCol;
    const float* Bptr = Bm + (long long)bRow * N + bx * 128 + bCol;

    float acc[8][8];
    #pragma unroll
    for (int i = 0; i < 8; i++)
        #pragma unroll
        for (int j = 0; j < 8; j++) acc[i][j] = 0.0f;

    for (int k0 = 0; k0 < K; k0 += 8) {
        float4 av = *(const float4*)Aptr;
        float4 bv = *(const float4*)Bptr;
        __syncthreads();
        As[aCol + 0][aRow] = av.x;
        As[aCol + 1][aRow] = av.y;
        As[aCol + 2][aRow] = av.z;
        As[aCol + 3][aRow] = av.w;
        *(float4*)&Bs[bRow][bCol] = bv;
        __syncthreads();
        #pragma unroll
        for (int kk = 0; kk < 8; kk++) {
            float4 a0 = *(const float4*)&As[kk][ty * 8];
            float4 a1 = *(const float4*)&As[kk][ty * 8 + 4];
            float4 b0 = *(const float4*)&Bs[kk][tx * 8];
            float4 b1 = *(const float4*)&Bs[kk][tx * 8 + 4];
            float a[8] = {a0.x, a0.y, a0.z, a0.w, a1.x, a1.y, a1.z, a1.w};
            float b[8] = {b0.x, b0.y, b0.z, b0.w, b1.x, b1.y, b1.z, b1.w};
            #pragma unroll
            for (int i = 0; i < 8; i++)
                #pragma unroll
                for (int j = 0; j < 8; j++)
                    acc[i][j] += a[i] * b[j];
        }
        Aptr += 8;
        Bptr += (long long)8 * N;
    }

    int rowC = by * 128 + ty * 8;
    int colC = bx * 128 + tx * 8;
    float bvals[8];
    if (act >= 1) {
        #pragma unroll
        for (int j = 0; j < 8; j++) bvals[j] = bias[colC + j];
    }
    #pragma unroll
    for (int i = 0; i < 8; i++) {
        float v[8];
        #pragma unroll
        for (int j = 0; j < 8; j++) {
            float t = acc[i][j];
            if (act >= 1) t += bvals[j];
            if (act == 2) t = gelu_tanh(t);
            v[j] = t;
        }
        float* cp = C + (long long)(rowC + i) * N + colC;
        *(float4*)cp       = make_float4(v[0], v[1], v[2], v[3]);
        *(float4*)(cp + 4) = make_float4(v[4], v[5], v[6], v[7]);
    }
}

// ---------------------------------------------------------------------------
// Attention pass 1: per (b,h), q-tile of 64 rows.
// S = scale * Q K^T written raw to tmp (b,h,n,m); online rowmax / rowsum.
// ---------------------------------------------------------------------------
__global__ void att_pass1(const float* __restrict__ q, const float* __restrict__ kv,
                          float* __restrict__ tmp, float* __restrict__ rowmax,
                          float* __restrict__ rowrl)
{
    int bh = blockIdx.y;
    int b = bh >> 4, h = bh & 15;
    int n0 = blockIdx.x * 64;

    __shared__ float Qs[64][68];   // [d][n] transposed
    __shared__ float Ks[64][68];   // [d][m] transposed
    __shared__ float runm[64], runl[64];

    int tid = threadIdx.x;
    int tx = tid & 15, ty = tid >> 4;

    for (int i = tid; i < 1024; i += 256) {
        int r = i >> 4, c4 = (i & 15) * 4;
        float4 v = *(const float4*)(q + ((size_t)(b * 1024 + n0 + r) * 1024) + h * 64 + c4);
        Qs[c4 + 0][r] = v.x; Qs[c4 + 1][r] = v.y;
        Qs[c4 + 2][r] = v.z; Qs[c4 + 3][r] = v.w;
    }
    if (tid < 64) { runm[tid] = -1e30f; runl[tid] = 0.0f; }

    const float scale = 0.125f;   // 64^-0.5

    for (int m0 = 0; m0 < 1024; m0 += 64) {
        __syncthreads();
        for (int i = tid; i < 1024; i += 256) {
            int r = i >> 4, c4 = (i & 15) * 4;
            float4 v = *(const float4*)(kv + ((size_t)(b * 1024 + m0 + r) * 2048) + h * 64 + c4);
            Ks[c4 + 0][r] = v.x; Ks[c4 + 1][r] = v.y;
            Ks[c4 + 2][r] = v.z; Ks[c4 + 3][r] = v.w;
        }
        __syncthreads();

        float acc[4][4];
        #pragma unroll
        for (int i = 0; i < 4; i++)
            #pragma unroll
            for (int j = 0; j < 4; j++) acc[i][j] = 0.0f;

        #pragma unroll 16
        for (int d = 0; d < 64; d++) {
            float4 a = *(const float4*)&Qs[d][ty * 4];
            float4 bb = *(const float4*)&Ks[d][tx * 4];
            float av[4] = {a.x, a.y, a.z, a.w};
            float bv[4] = {bb.x, bb.y, bb.z, bb.w};
            #pragma unroll
            for (int i = 0; i < 4; i++)
                #pragma unroll
                for (int j = 0; j < 4; j++)
                    acc[i][j] += av[i] * bv[j];
        }

        #pragma unroll
        for (int i = 0; i < 4; i++) {
            int r = ty * 4 + i;
            float s0 = acc[i][0] * scale, s1 = acc[i][1] * scale;
            float s2 = acc[i][2] * scale, s3 = acc[i][3] * scale;
            *(float4*)(tmp + ((size_t)bh * 1024 + n0 + r) * 1024 + m0 + tx * 4) =
                make_float4(s0, s1, s2, s3);
            float lm = fmaxf(fmaxf(s0, s1), fmaxf(s2, s3));
            lm = fmaxf(lm, __shfl_xor_sync(0xffffffffu, lm, 8));
            lm = fmaxf(lm, __shfl_xor_sync(0xffffffffu, lm, 4));
            lm = fmaxf(lm, __shfl_xor_sync(0xffffffffu, lm, 2));
            lm = fmaxf(lm, __shfl_xor_sync(0xffffffffu, lm, 1));
            float rm = runm[r];
            float nm = fmaxf(rm, lm);
            float es = __expf(s0 - nm) + __expf(s1 - nm) + __expf(s2 - nm) + __expf(s3 - nm);
            es += __shfl_xor_sync(0xffffffffu, es, 8);
            es += __shfl_xor_sync(0xffffffffu, es, 4);
            es += __shfl_xor_sync(0xffffffffu, es, 2);
            es += __shfl_xor_sync(0xffffffffu, es, 1);
            if (tx == 0) {
                runl[r] = runl[r] * __expf(rm - nm) + es;
                runm[r] = nm;
            }
        }
    }
    __syncthreads();
    if (tid < 64) {
        rowmax[(size_t)bh * 1024 + n0 + tid] = runm[tid];
        rowrl[(size_t)bh * 1024 + n0 + tid]  = 1.0f / runl[tid];
    }
}

// ---------------------------------------------------------------------------
// Attention pass 2: normalize tmp in place (final attn probs) and compute P@V.
// ---------------------------------------------------------------------------
__global__ void att_pass2(const float* __restrict__ kv, float* __restrict__ tmp,
                          const float* __restrict__ rowmax, const float* __restrict__ rowrl,
                          float* __restrict__ attout)
{
    int bh = blockIdx.y;
    int b = bh >> 4, h = bh & 15;
    int n0 = blockIdx.x * 64;

    __shared__ float Ps[64][68];   // [m][n]
    __shared__ float Vs[64][68];   // [m][d]
    __shared__ float rm_s[64], rl_s[64];

    int tid = threadIdx.x;
    int tx = tid & 15, ty = tid >> 4;

    if (tid < 64) {
        rm_s[tid] = rowmax[(size_t)bh * 1024 + n0 + tid];
        rl_s[tid] = rowrl[(size_t)bh * 1024 + n0 + tid];
    }

    float o[4][4];
    #pragma unroll
    for (int i = 0; i < 4; i++)
        #pragma unroll
        for (int j = 0; j < 4; j++) o[i][j] = 0.0f;

    for (int m0 = 0; m0 < 1024; m0 += 64) {
        __syncthreads();
        for (int i = tid; i < 1024; i += 256) {
            int r = i >> 4, c4 = (i & 15) * 4;
            *(float4*)&Vs[r][c4] =
                *(const float4*)(kv + ((size_t)(b * 1024 + m0 + r) * 2048) + 1024 + h * 64 + c4);
        }
        #pragma unroll
        for (int i = 0; i < 4; i++) {
            int r = ty * 4 + i;
            float* tp = tmp + ((size_t)bh * 1024 + n0 + r) * 1024 + m0 + tx * 4;
            float4 s4 = *(const float4*)tp;
            float rm = rm_s[r], rl = rl_s[r];
            float p0 = __expf(s4.x - rm) * rl;
            float p1 = __expf(s4.y - rm) * rl;
            float p2 = __expf(s4.z - rm) * rl;
            float p3 = __expf(s4.w - rm) * rl;
            *(float4*)tp = make_float4(p0, p1, p2, p3);
            Ps[tx * 4 + 0][r] = p0;
            Ps[tx * 4 + 1][r] = p1;
            Ps[tx * 4 + 2][r] = p2;
            Ps[tx * 4 + 3][r] = p3;
        }
        __syncthreads();
        #pragma unroll 16
        for (int m = 0; m < 64; m++) {
            float4 a = *(const float4*)&Ps[m][ty * 4];
            float4 bb = *(const float4*)&Vs[m][tx * 4];
            float av[4] = {a.x, a.y, a.z, a.w};
            float bv[4] = {bb.x, bb.y, bb.z, bb.w};
            #pragma unroll
            for (int i = 0; i < 4; i++)
                #pragma unroll
                for (int j = 0; j < 4; j++)
                    o[i][j] += av[i] * bv[j];
        }
    }

    #pragma unroll
    for (int i = 0; i < 4; i++) {
        int r = ty * 4 + i;
        *(float4*)(attout + ((size_t)(b * 1024 + n0 + r) * 1024) + h * 64 + tx * 4) =
            make_float4(o[i][0], o[i][1], o[i][2], o[i][3]);
    }
}

// ---------------------------------------------------------------------------
// Transpose attn scratch (b,h,n,m) -> output (b,n,m,h). Fully coalesced.
// ---------------------------------------------------------------------------
__global__ void attn_tr(const float* __restrict__ tmp, float* __restrict__ outAttn)
{
    int b = blockIdx.z;
    int n = blockIdx.y;
    int m0 = blockIdx.x * 256;
    __shared__ float T[16][257];
    int tid = threadIdx.x;
    for (int i = tid; i < 16 * 256; i += 256) {
        int hh = i >> 8, mm = i & 255;
        T[hh][mm] = tmp[((size_t)(b * 16 + hh) * 1024 + n) * 1024 + m0 + mm];
    }
    __syncthreads();
    float* dst = outAttn + ((size_t)(b * 1024 + n) * 1024 + m0 + tid) * 16;
    #pragma unroll
    for (int k = 0; k < 16; k += 4) {
        *(float4*)(dst + k) = make_float4(T[k][tid], T[k + 1][tid], T[k + 2][tid], T[k + 3][tid]);
    }
}

// ---------------------------------------------------------------------------
// Row softmax over contiguous 1024 (combine weights).
// ---------------------------------------------------------------------------
__global__ void row_softmax(const float* __restrict__ in, float* __restrict__ outp)
{
    size_t row = blockIdx.x;
    const float4* L = (const float4*)(in + row * 1024);
    float4* O = (float4*)(outp + row * 1024);
    int t = threadIdx.x;
    float4 v = L[t];
    float mx = fmaxf(fmaxf(v.x, v.y), fmaxf(v.z, v.w));
    __shared__ float smA[8], smB[8];
    #pragma unroll
    for (int off = 16; off; off >>= 1) mx = fmaxf(mx, __shfl_xor_sync(0xffffffffu, mx, off));
    if ((t & 31) == 0) smA[t >> 5] = mx;
    __syncthreads();
    mx = smA[0];
    #pragma unroll
    for (int w = 1; w < 8; w++) mx = fmaxf(mx, smA[w]);
    float e0 = __expf(v.x - mx), e1 = __expf(v.y - mx);
    float e2 = __expf(v.z - mx), e3 = __expf(v.w - mx);
    float s = e0 + e1 + e2 + e3;
    #pragma unroll
    for (int off = 16; off; off >>= 1) s += __shfl_xor_sync(0xffffffffu, s, off);
    if ((t & 31) == 0) smB[t >> 5] = s;
    __syncthreads();
    s = 0.0f;
    #pragma unroll
    for (int w = 0; w < 8; w++) s += smB[w];
    float r = 1.0f / s;
    O[t] = make_float4(e0 * r, e1 * r, e2 * r, e3 * r);
}

// ---------------------------------------------------------------------------
// Dispatch softmax over token axis n (column softmax of (n,1024) per batch),
// written TRANSPOSED: dispT[b][es][n], so `slots` becomes a plain GEMM.
// ---------------------------------------------------------------------------
__global__ void disp_softmax(const float* __restrict__ logits, float* __restrict__ dispT)
{
    int b = blockIdx.y;
    int c0 = blockIdx.x * 64;
    const float* L = logits + (size_t)b * 1048576;
    float* O = dispT + (size_t)b * 1048576;
    int tid = threadIdx.x;
    int tx = tid & 63, ty = tid >> 6;   // 4 x 64
    int col = c0 + tx;

    __shared__ float red[4][64];
    float mx = -1e30f;
    for (int n = ty; n < 1024; n += 4) mx = fmaxf(mx, L[(size_t)n * 1024 + col]);
    red[ty][tx] = mx;
    __syncthreads();
    mx = fmaxf(fmaxf(red[0][tx], red[1][tx]), fmaxf(red[2][tx], red[3][tx]));
    __syncthreads();
    float s = 0.0f;
    for (int n = ty; n < 1024; n += 4) s += __expf(L[(size_t)n * 1024 + col] - mx);
    red[ty][tx] = s;
    __syncthreads();
    s = red[0][tx] + red[1][tx] + red[2][tx] + red[3][tx];
    float rinv = 1.0f / s;
    __syncthreads();

    __shared__ float T[64][65];
    for (int n0 = 0; n0 < 1024; n0 += 64) {
        for (int n = ty; n < 64; n += 4)
            T[tx][n] = __expf(L[(size_t)(n0 + n) * 1024 + col] - mx) * rinv;
        __syncthreads();
        int cl = tid >> 2;
        int nl = (tid & 3) * 16;
        float* dst = O + (size_t)(c0 + cl) * 1024 + n0 + nl;
        #pragma unroll
        for (int k = 0; k < 16; k += 4)
            *(float4*)(dst + k) = make_float4(T[cl][nl + k], T[cl][nl + k + 1],
                                              T[cl][nl + k + 2], T[cl][nl + k + 3]);
        __syncthreads();
    }
}

// ---------------------------------------------------------------------------
// Fused residual + LayerNorm: out = LN(a + coefb * bsrc) * g + beta
// ---------------------------------------------------------------------------
__global__ void ln_res(const float* __restrict__ a, const float* __restrict__ bsrc,
                       float coefb, const float* __restrict__ g,
                       const float* __restrict__ beta, float* __restrict__ outp)
{
    size_t row = blockIdx.x;
    int t = threadIdx.x;
    float4 av = ((const float4*)(a + row * 1024))[t];
    float4 bv = ((const float4*)(bsrc + row * 1024))[t];
    float x0 = av.x + coefb * bv.x;
    float x1 = av.y + coefb * bv.y;
    float x2 = av.z + coefb * bv.z;
    float x3 = av.w + coefb * bv.w;
    float s = x0 + x1 + x2 + x3;
    float q = x0 * x0 + x1 * x1 + x2 * x2 + x3 * x3;
    __shared__ float smA[8], smB[8];
    #pragma unroll
    for (int off = 16; off; off >>= 1) {
        s += __shfl_xor_sync(0xffffffffu, s, off);
        q += __shfl_xor_sync(0xffffffffu, q, off);
    }
    if ((t & 31) == 0) { smA[t >> 5] = s; smB[t >> 5] = q; }
    __syncthreads();
    s = 0.0f; q = 0.0f;
    #pragma unroll
    for (int w = 0; w < 8; w++) { s += smA[w]; q += smB[w]; }
    float mu = s * (1.0f / 1024.0f);
    float var = q * (1.0f / 1024.0f) - mu * mu;
    float rs = rsqrtf(var + 1e-5f);
    float4 gv = ((const float4*)g)[t];
    float4 btv = ((const float4*)beta)[t];
    float4 out4;
    out4.x = (x0 - mu) * rs * gv.x + btv.x;
    out4.y = (x1 - mu) * rs * gv.y + btv.y;
    out4.z = (x2 - mu) * rs * gv.z + btv.z;
    out4.w = (x3 - mu) * rs * gv.w + btv.w;
    ((float4*)(outp + row * 1024))[t] = out4;
}

// ---------------------------------------------------------------------------
// Launcher
// ---------------------------------------------------------------------------
extern "C" void kernel_launch(void* const* d_in, const int* in_sizes, int n_in,
                              void* d_out, int out_size)
{
    const float* x   = (const float*)d_in[0];
    const float* Wq  = (const float*)d_in[1];
    const float* bq  = (const float*)d_in[2];
    const float* Wkv = (const float*)d_in[3];
    const float* bkv = (const float*)d_in[4];
    const float* Wp  = (const float*)d_in[5];
    const float* bp  = (const float*)d_in[6];
    const float* g1  = (const float*)d_in[7];
    const float* b1  = (const float*)d_in[8];
    const float* phi = (const float*)d_in[9];
    const float* We1 = (const float*)d_in[10];
    const float* be1 = (const float*)d_in[11];
    const float* We2 = (const float*)d_in[12];
    const float* be2 = (const float*)d_in[13];
    const float* g2  = (const float*)d_in[14];
    const float* b2  = (const float*)d_in[15];

    float* arena = nullptr;
    cudaGetSymbolAddress((void**)&arena, g_arena);

    float* q      = arena + OFF_Q;
    float* kvb    = arena + OFF_KV;
    float* tmp    = arena + OFF_TMP;
    float* attout = arena + OFF_ATTOUT;
    float* proj   = arena + OFF_PROJ;
    float* x1     = arena + OFF_X1;
    float* logits = arena + OFF_LOGITS;
    float* dispT  = arena + OFF_DISPT;
    float* comb   = arena + OFF_COMB;
    float* slots  = arena + OFF_SLOTS;
    float* hbuf   = arena + OFF_H;
    float* ymoe   = arena + OFF_YMOE;
    float* moeout = arena + OFF_MOE;
    float* rm     = arena + OFF_RM;
    float* rl     = arena + OFF_RL;

    float* out = (float*)d_out;
    float* outAttn = out + 4194304;

    dim3 T(256);

    // q = x @ Wq + bq          (4096x1024x1024)
    sgemm<<<dim3(8, 32, 1), T>>>(x, Wq, bq, q, 4096, 1024, 1024, 0, 0, 0, 0, 1, 1);
    // kv = x @ Wkv + bkv       (4096x2048x1024)
    sgemm<<<dim3(16, 32, 1), T>>>(x, Wkv, bkv, kvb, 4096, 2048, 1024, 0, 0, 0, 0, 1, 1);

    // attention
    att_pass1<<<dim3(16, 64), T>>>(q, kvb, tmp, rm, rl);
    att_pass2<<<dim3(16, 64), T>>>(kvb, tmp, rm, rl, attout);
    attn_tr<<<dim3(4, 1024, 4), T>>>(tmp, outAttn);

    // out-proj + residual LN
    sgemm<<<dim3(8, 32, 1), T>>>(attout, Wp, bp, proj, 4096, 1024, 1024, 0, 0, 0, 0, 1, 1);
    ln_res<<<4096, T>>>(proj, x, 1.0f, g1, b1, x1);

    // soft-MoE
    sgemm<<<dim3(8, 32, 1), T>>>(x1, phi, nullptr, logits, 4096, 1024, 1024, 0, 0, 0, 0, 1, 0);
    row_softmax<<<4096, T>>>(logits, comb);
    disp_softmax<<<dim3(16, 4), T>>>(logits, dispT);

    // slots[b] = dispT[b] @ x1[b]   (batched over b)
    sgemm<<<dim3(8, 8, 4), T>>>(dispT, x1, nullptr, slots, 1024, 1024, 1024,
                                1048576, 1048576, 0, 1048576, 0, 0);
    // h = gelu(slots @ We1[e] + be1[e])   (batched over (b,e), e = z % 2)
    sgemm<<<dim3(32, 4, 8), T>>>(slots, We1, be1, hbuf, 512, 4096, 1024,
                                 524288, 4194304, 4096, 2097152, 2, 2);
    // y = h @ We2[e] + be2[e]
    sgemm<<<dim3(8, 4, 8), T>>>(hbuf, We2, be2, ymoe, 512, 1024, 4096,
                                2097152, 4194304, 1024, 524288, 2, 1);
    // moe_out[b] = comb[b] @ ymoe[b]
    sgemm<<<dim3(8, 8, 4), T>>>(comb, ymoe, nullptr, moeout, 1024, 1024, 1024,
                                1048576, 1048576, 0, 1048576, 0, 0);

    // y = LN(moe_out + 2*x1)
    ln_res<<<4096, T>>>(moeout, x1, 2.0f, g2, b2, out);
}

// round 2
// speedup vs baseline: 2.5578x; 2.5578x over previous
#include <cuda_runtime.h>
#include <math.h>
#include <stdint.h>

// ---------------------------------------------------------------------------
// Problem constants
//   B=4, SEQ=1024, DIM=1024, HEADS=16, HD=64, N_EXP=2, SLOTS=512, HID=4096
// Output: [ y : 4*1024*1024 f32 ][ attn : 4*1024*1024*16 f32 ]
// ---------------------------------------------------------------------------

#define OFF_Q       0LL
#define OFF_KV      4194304LL
#define OFF_TMP     12582912LL     // attn scratch (b,h,n,m) 64M floats
#define OFF_ATTOUT  79691776LL
#define OFF_PROJ    83886080LL
#define OFF_X1      88080384LL
#define OFF_LOGITS  92274688LL
#define OFF_DISPT   96468992LL
#define OFF_COMB    100663296LL
#define OFF_SLOTS   104857600LL
#define OFF_H       109051904LL    // 16M floats
#define OFF_YMOE    125829120LL
#define OFF_MOE     130023424LL
#define OFF_RM      134217728LL
#define OFF_RL      134283264LL
#define ARENA_FLOATS 134348800LL

__device__ float g_arena[ARENA_FLOATS];

__device__ __forceinline__ float gelu_tanh(float v) {
    const float c0 = 0.7978845608028654f;   // sqrt(2/pi)
    float t = tanhf(c0 * (v + 0.044715f * v * v * v));
    return 0.5f * v * (1.0f + t);
}

__device__ __forceinline__ float to_tf32(float x) {
    float r;
    asm("cvt.rna.tf32.f32 %0, %1;" : "=f"(r) : "f"(x));
    return r;
}

// ---------------------------------------------------------------------------
// tf32 tensor-core batched GEMM: C = A(MxK) @ B(KxN) [+bias] [gelu]
// Row-major. M,N multiples of 128, K multiple of 16.
// Block 256 threads = 8 warps (2x4), warp tile 64x32, mma m16n8k8.
// batch z: A += z*sA, B += zb*sB (zb = nBmod? z%nBmod : z), C += z*sC
// act: 0 none, 1 +bias, 2 +bias+gelu
// ---------------------------------------------------------------------------
__global__ void __launch_bounds__(256, 2)
tgemm(const float* __restrict__ A, const float* __restrict__ Bm,
      const float* __restrict__ bias, float* __restrict__ C,
      int M, int N, int K,
      long long sA, long long sB, long long sBias, long long sC,
      int nBmod, int act)
{
    int z = blockIdx.z;
    int zb = nBmod ? (z % nBmod) : z;
    A  += (long long)z * sA;
    Bm += (long long)zb * sB;
    if (act >= 1) bias += (long long)zb * sBias;
    C  += (long long)z * sC;

    __shared__ float As[128][20];   // [m][k], k-tile 16 padded to 20 (bank-clean frag reads)
    __shared__ float Bs[16][136];   // [k][n], n-tile 128 padded to 136 (bank-clean frag reads)

    int bx = blockIdx.x, by = blockIdx.y;
    int tid = threadIdx.x;
    int wid = tid >> 5;
    int lane = tid & 31;
    int g = lane >> 2;      // 0..7
    int j = lane & 3;       // 0..3
    int warp_m = wid >> 2;  // 0..1
    int warp_n = wid & 3;   // 0..3
    int wm64 = warp_m * 64;
    int wn32 = warp_n * 32;

    // gmem load mapping (2 float4 each for A and B per thread per k16)
    int aRow0 = tid >> 2;            // 0..63
    int aKc   = (tid & 3) * 4;       // 0,4,8,12
    int bRow0 = tid >> 5;            // 0..7
    int bCc   = (tid & 31) * 4;      // 0..124

    const float* Ap0 = A + (long long)(by * 128 + aRow0)      * K + aKc;
    const float* Ap1 = A + (long long)(by * 128 + aRow0 + 64) * K + aKc;
    const float* Bp0 = Bm + (long long)(bRow0)     * N + bx * 128 + bCc;
    const float* Bp1 = Bm + (long long)(bRow0 + 8) * N + bx * 128 + bCc;

    float c[4][4][4];
    #pragma unroll
    for (int mt = 0; mt < 4; mt++)
        #pragma unroll
        for (int nt = 0; nt < 4; nt++)
            #pragma unroll
            for (int r = 0; r < 4; r++) c[mt][nt][r] = 0.0f;

    // prefetch first tile
    float4 av0 = *(const float4*)Ap0;
    float4 av1 = *(const float4*)Ap1;
    float4 bv0 = *(const float4*)Bp0;
    float4 bv1 = *(const float4*)Bp1;

    for (int k0 = 0; k0 < K; k0 += 16) {
        __syncthreads();
        // store (with tf32 rounding) into smem
        {
            float4 t;
            t.x = to_tf32(av0.x); t.y = to_tf32(av0.y); t.z = to_tf32(av0.z); t.w = to_tf32(av0.w);
            *(float4*)&As[aRow0][aKc] = t;
            t.x = to_tf32(av1.x); t.y = to_tf32(av1.y); t.z = to_tf32(av1.z); t.w = to_tf32(av1.w);
            *(float4*)&As[aRow0 + 64][aKc] = t;
            t.x = to_tf32(bv0.x); t.y = to_tf32(bv0.y); t.z = to_tf32(bv0.z); t.w = to_tf32(bv0.w);
            *(float4*)&Bs[bRow0][bCc] = t;
            t.x = to_tf32(bv1.x); t.y = to_tf32(bv1.y); t.z = to_tf32(bv1.z); t.w = to_tf32(bv1.w);
            *(float4*)&Bs[bRow0 + 8][bCc] = t;
        }
        __syncthreads();

        // prefetch next tile (overlaps with mma compute below)
        if (k0 + 16 < K) {
            Ap0 += 16; Ap1 += 16;
            Bp0 += (long long)16 * N; Bp1 += (long long)16 * N;
            av0 = *(const float4*)Ap0;
            av1 = *(const float4*)Ap1;
            bv0 = *(const float4*)Bp0;
            bv1 = *(const float4*)Bp1;
        }

        #pragma unroll
        for (int kk = 0; kk < 16; kk += 8) {
            uint32_t a[4][4];
            uint32_t bfr[4][2];
            #pragma unroll
            for (int mt = 0; mt < 4; mt++) {
                const float* p = &As[wm64 + mt * 16 + g][kk + j];
                a[mt][0] = __float_as_uint(p[0]);
                a[mt][1] = __float_as_uint(p[8 * 20]);
                a[mt][2] = __float_as_uint(p[4]);
                a[mt][3] = __float_as_uint(p[8 * 20 + 4]);
            }
            #pragma unroll
            for (int nt = 0; nt < 4; nt++) {
                const float* p = &Bs[kk + j][wn32 + nt * 8 + g];
                bfr[nt][0] = __float_as_uint(p[0]);
                bfr[nt][1] = __float_as_uint(p[4 * 136]);
            }
            #pragma unroll
            for (int mt = 0; mt < 4; mt++)
                #pragma unroll
                for (int nt = 0; nt < 4; nt++) {
                    asm volatile(
                        "mma.sync.aligned.m16n8k8.row.col.f32.tf32.tf32.f32 "
                        "{%0,%1,%2,%3},{%4,%5,%6,%7},{%8,%9},{%0,%1,%2,%3};"
                        : "+f"(c[mt][nt][0]), "+f"(c[mt][nt][1]),
                          "+f"(c[mt][nt][2]), "+f"(c[mt][nt][3])
                        : "r"(a[mt][0]), "r"(a[mt][1]), "r"(a[mt][2]), "r"(a[mt][3]),
                          "r"(bfr[nt][0]), "r"(bfr[nt][1]));
                }
        }
    }

    // epilogue
    #pragma unroll
    for (int mt = 0; mt < 4; mt++) {
        int r0 = by * 128 + wm64 + mt * 16 + g;
        #pragma unroll
        for (int nt = 0; nt < 4; nt++) {
            int col = bx * 128 + wn32 + nt * 8 + 2 * j;
            float b0 = 0.0f, b1 = 0.0f;
            if (act >= 1) { b0 = bias[col]; b1 = bias[col + 1]; }
            float v0 = c[mt][nt][0] + b0;
            float v1 = c[mt][nt][1] + b1;
            float v2 = c[mt][nt][2] + b0;
            float v3 = c[mt][nt][3] + b1;
            if (act == 2) {
                v0 = gelu_tanh(v0); v1 = gelu_tanh(v1);
                v2 = gelu_tanh(v2); v3 = gelu_tanh(v3);
            }
            *(float2*)(C + (long long)r0 * N + col)       = make_float2(v0, v1);
            *(float2*)(C + (long long)(r0 + 8) * N + col) = make_float2(v2, v3);
        }
    }
}

// ---------------------------------------------------------------------------
// Attention pass 1: per (b,h), q-tile of 64 rows.
// S = scale * Q K^T written raw to tmp (b,h,n,m); online rowmax / rowsum.
// ---------------------------------------------------------------------------
__global__ void att_pass1(const float* __restrict__ q, const float* __restrict__ kv,
                          float* __restrict__ tmp, float* __restrict__ rowmax,
                          float* __restrict__ rowrl)
{
    int bh = blockIdx.y;
    int b = bh >> 4, h = bh & 15;
    int n0 = blockIdx.x * 64;

    __shared__ float Qs[64][68];   // [d][n] transposed
    __shared__ float Ks[64][68];   // [d][m] transposed
    __shared__ float runm[64], runl[64];

    int tid = threadIdx.x;
    int tx = tid & 15, ty = tid >> 4;

    for (int i = tid; i < 1024; i += 256) {
        int r = i >> 4, c4 = (i & 15) * 4;
        float4 v = *(const float4*)(q + ((size_t)(b * 1024 + n0 + r) * 1024) + h * 64 + c4);
        Qs[c4 + 0][r] = v.x; Qs[c4 + 1][r] = v.y;
        Qs[c4 + 2][r] = v.z; Qs[c4 + 3][r] = v.w;
    }
    if (tid < 64) { runm[tid] = -1e30f; runl[tid] = 0.0f; }

    const float scale = 0.125f;   // 64^-0.5

    for (int m0 = 0; m0 < 1024; m0 += 64) {
        __syncthreads();
        for (int i = tid; i < 1024; i += 256) {
            int r = i >> 4, c4 = (i & 15) * 4;
            float4 v = *(const float4*)(kv + ((size_t)(b * 1024 + m0 + r) * 2048) + h * 64 + c4);
            Ks[c4 + 0][r] = v.x; Ks[c4 + 1][r] = v.y;
            Ks[c4 + 2][r] = v.z; Ks[c4 + 3][r] = v.w;
        }
        __syncthreads();

        float acc[4][4];
        #pragma unroll
        for (int i = 0; i < 4; i++)
            #pragma unroll
            for (int j = 0; j < 4; j++) acc[i][j] = 0.0f;

        #pragma unroll 16
        for (int d = 0; d < 64; d++) {
            float4 a = *(const float4*)&Qs[d][ty * 4];
            float4 bb = *(const float4*)&Ks[d][tx * 4];
            float av[4] = {a.x, a.y, a.z, a.w};
            float bv[4] = {bb.x, bb.y, bb.z, bb.w};
            #pragma unroll
            for (int i = 0; i < 4; i++)
                #pragma unroll
                for (int j = 0; j < 4; j++)
                    acc[i][j] += av[i] * bv[j];
        }

        #pragma unroll
        for (int i = 0; i < 4; i++) {
            int r = ty * 4 + i;
            float s0 = acc[i][0] * scale, s1 = acc[i][1] * scale;
            float s2 = acc[i][2] * scale, s3 = acc[i][3] * scale;
            *(float4*)(tmp + ((size_t)bh * 1024 + n0 + r) * 1024 + m0 + tx * 4) =
                make_float4(s0, s1, s2, s3);
            float lm = fmaxf(fmaxf(s0, s1), fmaxf(s2, s3));
            lm = fmaxf(lm, __shfl_xor_sync(0xffffffffu, lm, 8));
            lm = fmaxf(lm, __shfl_xor_sync(0xffffffffu, lm, 4));
            lm = fmaxf(lm, __shfl_xor_sync(0xffffffffu, lm, 2));
            lm = fmaxf(lm, __shfl_xor_sync(0xffffffffu, lm, 1));
            float rm = runm[r];
            float nm = fmaxf(rm, lm);
            float es = __expf(s0 - nm) + __expf(s1 - nm) + __expf(s2 - nm) + __expf(s3 - nm);
            es += __shfl_xor_sync(0xffffffffu, es, 8);
            es += __shfl_xor_sync(0xffffffffu, es, 4);
            es += __shfl_xor_sync(0xffffffffu, es, 2);
            es += __shfl_xor_sync(0xffffffffu, es, 1);
            if (tx == 0) {
                runl[r] = runl[r] * __expf(rm - nm) + es;
                runm[r] = nm;
            }
        }
    }
    __syncthreads();
    if (tid < 64) {
        rowmax[(size_t)bh * 1024 + n0 + tid] = runm[tid];
        rowrl[(size_t)bh * 1024 + n0 + tid]  = 1.0f / runl[tid];
    }
}

// ---------------------------------------------------------------------------
// Attention pass 2: normalize tmp in place (final attn probs) and compute P@V.
// ---------------------------------------------------------------------------
__global__ void att_pass2(const float* __restrict__ kv, float* __restrict__ tmp,
                          const float* __restrict__ rowmax, const float* __restrict__ rowrl,
                          float* __restrict__ attout)
{
    int bh = blockIdx.y;
    int b = bh >> 4, h = bh & 15;
    int n0 = blockIdx.x * 64;

    __shared__ float Ps[64][68];   // [m][n]
    __shared__ float Vs[64][68];   // [m][d]
    __shared__ float rm_s[64], rl_s[64];

    int tid = threadIdx.x;
    int tx = tid & 15, ty = tid >> 4;

    if (tid < 64) {
        rm_s[tid] = rowmax[(size_t)bh * 1024 + n0 + tid];
        rl_s[tid] = rowrl[(size_t)bh * 1024 + n0 + tid];
    }

    float o[4][4];
    #pragma unroll
    for (int i = 0; i < 4; i++)
        #pragma unroll
        for (int j = 0; j < 4; j++) o[i][j] = 0.0f;

    for (int m0 = 0; m0 < 1024; m0 += 64) {
        __syncthreads();
        for (int i = tid; i < 1024; i += 256) {
            int r = i >> 4, c4 = (i & 15) * 4;
            *(float4*)&Vs[r][c4] =
                *(const float4*)(kv + ((size_t)(b * 1024 + m0 + r) * 2048) + 1024 + h * 64 + c4);
        }
        #pragma unroll
        for (int i = 0; i < 4; i++) {
            int r = ty * 4 + i;
            float* tp = tmp + ((size_t)bh * 1024 + n0 + r) * 1024 + m0 + tx * 4;
            float4 s4 = *(const float4*)tp;
            float rm = rm_s[r], rl = rl_s[r];
            float p0 = __expf(s4.x - rm) * rl;
            float p1 = __expf(s4.y - rm) * rl;
            float p2 = __expf(s4.z - rm) * rl;
            float p3 = __expf(s4.w - rm) * rl;
            *(float4*)tp = make_float4(p0, p1, p2, p3);
            Ps[tx * 4 + 0][r] = p0;
            Ps[tx * 4 + 1][r] = p1;
            Ps[tx * 4 + 2][r] = p2;
            Ps[tx * 4 + 3][r] = p3;
        }
        __syncthreads();
        #pragma unroll 16
        for (int m = 0; m < 64; m++) {
            float4 a = *(const float4*)&Ps[m][ty * 4];
            float4 bb = *(const float4*)&Vs[m][tx * 4];
            float av[4] = {a.x, a.y, a.z, a.w};
            float bv[4] = {bb.x, bb.y, bb.z, bb.w};
            #pragma unroll
            for (int i = 0; i < 4; i++)
                #pragma unroll
                for (int j = 0; j < 4; j++)
                    o[i][j] += av[i] * bv[j];
        }
    }

    #pragma unroll
    for (int i = 0; i < 4; i++) {
        int r = ty * 4 + i;
        *(float4*)(attout + ((size_t)(b * 1024 + n0 + r) * 1024) + h * 64 + tx * 4) =
            make_float4(o[i][0], o[i][1], o[i][2], o[i][3]);
    }
}

// ---------------------------------------------------------------------------
// Transpose attn scratch (b,h,n,m) -> output (b,n,m,h). Fully coalesced.
// ---------------------------------------------------------------------------
__global__ void attn_tr(const float* __restrict__ tmp, float* __restrict__ outAttn)
{
    int b = blockIdx.z;
    int n = blockIdx.y;
    int m0 = blockIdx.x * 256;
    __shared__ float T[16][257];
    int tid = threadIdx.x;
    for (int i = tid; i < 16 * 256; i += 256) {
        int hh = i >> 8, mm = i & 255;
        T[hh][mm] = tmp[((size_t)(b * 16 + hh) * 1024 + n) * 1024 + m0 + mm];
    }
    __syncthreads();
    float* dst = outAttn + ((size_t)(b * 1024 + n) * 1024 + m0 + tid) * 16;
    #pragma unroll
    for (int k = 0; k < 16; k += 4) {
        *(float4*)(dst + k) = make_float4(T[k][tid], T[k + 1][tid], T[k + 2][tid], T[k + 3][tid]);
    }
}

// ---------------------------------------------------------------------------
// Row softmax over contiguous 1024 (combine weights).
// ---------------------------------------------------------------------------
__global__ void row_softmax(const float* __restrict__ in, float* __restrict__ outp)
{
    size_t row = blockIdx.x;
    const float4* L = (const float4*)(in + row * 1024);
    float4* O = (float4*)(outp + row * 1024);
    int t = threadIdx.x;
    float4 v = L[t];
    float mx = fmaxf(fmaxf(v.x, v.y), fmaxf(v.z, v.w));
    __shared__ float smA[8], smB[8];
    #pragma unroll
    for (int off = 16; off; off >>= 1) mx = fmaxf(mx, __shfl_xor_sync(0xffffffffu, mx, off));
    if ((t & 31) == 0) smA[t >> 5] = mx;
    __syncthreads();
    mx = smA[0];
    #pragma unroll
    for (int w = 1; w < 8; w++) mx = fmaxf(mx, smA[w]);
    float e0 = __expf(v.x - mx), e1 = __expf(v.y - mx);
    float e2 = __expf(v.z - mx), e3 = __expf(v.w - mx);
    float s = e0 + e1 + e2 + e3;
    #pragma unroll
    for (int off = 16; off; off >>= 1) s += __shfl_xor_sync(0xffffffffu, s, off);
    if ((t & 31) == 0) smB[t >> 5] = s;
    __syncthreads();
    s = 0.0f;
    #pragma unroll
    for (int w = 0; w < 8; w++) s += smB[w];
    float r = 1.0f / s;
    O[t] = make_float4(e0 * r, e1 * r, e2 * r, e3 * r);
}

// ---------------------------------------------------------------------------
// Dispatch softmax over token axis n (column softmax of (n,1024) per batch),
// written TRANSPOSED: dispT[b][es][n], so `slots` becomes a plain GEMM.
// ---------------------------------------------------------------------------
__global__ void disp_softmax(const float* __restrict__ logits, float* __restrict__ dispT)
{
    int b = blockIdx.y;
    int c0 = blockIdx.x * 64;
    const float* L = logits + (size_t)b * 1048576;
    float* O = dispT + (size_t)b * 1048576;
    int tid = threadIdx.x;
    int tx = tid & 63, ty = tid >> 6;   // 4 x 64
    int col = c0 + tx;

    __shared__ float red[4][64];
    float mx = -1e30f;
    for (int n = ty; n < 1024; n += 4) mx = fmaxf(mx, L[(size_t)n * 1024 + col]);
    red[ty][tx] = mx;
    __syncthreads();
    mx = fmaxf(fmaxf(red[0][tx], red[1][tx]), fmaxf(red[2][tx], red[3][tx]));
    __syncthreads();
    float s = 0.0f;
    for (int n = ty; n < 1024; n += 4) s += __expf(L[(size_t)n * 1024 + col] - mx);
    red[ty][tx] = s;
    __syncthreads();
    s = red[0][tx] + red[1][tx] + red[2][tx] + red[3][tx];
    float rinv = 1.0f / s;
    __syncthreads();

    __shared__ float T[64][65];
    for (int n0 = 0; n0 < 1024; n0 += 64) {
        for (int n = ty; n < 64; n += 4)
            T[tx][n] = __expf(L[(size_t)(n0 + n) * 1024 + col] - mx) * rinv;
        __syncthreads();
        int cl = tid >> 2;
        int nl = (tid & 3) * 16;
        float* dst = O + (size_t)(c0 + cl) * 1024 + n0 + nl;
        #pragma unroll
        for (int k = 0; k < 16; k += 4)
            *(float4*)(dst + k) = make_float4(T[cl][nl + k], T[cl][nl + k + 1],
                                              T[cl][nl + k + 2], T[cl][nl + k + 3]);
        __syncthreads();
    }
}

// ---------------------------------------------------------------------------
// Fused residual + LayerNorm: out = LN(a + coefb * bsrc) * g + beta
// ---------------------------------------------------------------------------
__global__ void ln_res(const float* __restrict__ a, const float* __restrict__ bsrc,
                       float coefb, const float* __restrict__ g,
                       const float* __restrict__ beta, float* __restrict__ outp)
{
    size_t row = blockIdx.x;
    int t = threadIdx.x;
    float4 av = ((const float4*)(a + row * 1024))[t];
    float4 bv = ((const float4*)(bsrc + row * 1024))[t];
    float x0 = av.x + coefb * bv.x;
    float x1 = av.y + coefb * bv.y;
    float x2 = av.z + coefb * bv.z;
    float x3 = av.w + coefb * bv.w;
    float s = x0 + x1 + x2 + x3;
    float q = x0 * x0 + x1 * x1 + x2 * x2 + x3 * x3;
    __shared__ float smA[8], smB[8];
    #pragma unroll
    for (int off = 16; off; off >>= 1) {
        s += __shfl_xor_sync(0xffffffffu, s, off);
        q += __shfl_xor_sync(0xffffffffu, q, off);
    }
    if ((t & 31) == 0) { smA[t >> 5] = s; smB[t >> 5] = q; }
    __syncthreads();
    s = 0.0f; q = 0.0f;
    #pragma unroll
    for (int w = 0; w < 8; w++) { s += smA[w]; q += smB[w]; }
    float mu = s * (1.0f / 1024.0f);
    float var = q * (1.0f / 1024.0f) - mu * mu;
    float rs = rsqrtf(var + 1e-5f);
    float4 gv = ((const float4*)g)[t];
    float4 btv = ((const float4*)beta)[t];
    float4 out4;
    out4.x = (x0 - mu) * rs * gv.x + btv.x;
    out4.y = (x1 - mu) * rs * gv.y + btv.y;
    out4.z = (x2 - mu) * rs * gv.z + btv.z;
    out4.w = (x3 - mu) * rs * gv.w + btv.w;
    ((float4*)(outp + row * 1024))[t] = out4;
}

// ---------------------------------------------------------------------------
// Launcher
// ---------------------------------------------------------------------------
extern "C" void kernel_launch(void* const* d_in, const int* in_sizes, int n_in,
                              void* d_out, int out_size)
{
    const float* x   = (const float*)d_in[0];
    const float* Wq  = (const float*)d_in[1];
    const float* bq  = (const float*)d_in[2];
    const float* Wkv = (const float*)d_in[3];
    const float* bkv = (const float*)d_in[4];
    const float* Wp  = (const float*)d_in[5];
    const float* bp  = (const float*)d_in[6];
    const float* g1  = (const float*)d_in[7];
    const float* b1  = (const float*)d_in[8];
    const float* phi = (const float*)d_in[9];
    const float* We1 = (const float*)d_in[10];
    const float* be1 = (const float*)d_in[11];
    const float* We2 = (const float*)d_in[12];
    const float* be2 = (const float*)d_in[13];
    const float* g2  = (const float*)d_in[14];
    const float* b2  = (const float*)d_in[15];

    float* arena = nullptr;
    cudaGetSymbolAddress((void**)&arena, g_arena);

    float* q      = arena + OFF_Q;
    float* kvb    = arena + OFF_KV;
    float* tmp    = arena + OFF_TMP;
    float* attout = arena + OFF_ATTOUT;
    float* proj   = arena + OFF_PROJ;
    float* x1     = arena + OFF_X1;
    float* logits = arena + OFF_LOGITS;
    float* dispT  = arena + OFF_DISPT;
    float* comb   = arena + OFF_COMB;
    float* slots  = arena + OFF_SLOTS;
    float* hbuf   = arena + OFF_H;
    float* ymoe   = arena + OFF_YMOE;
    float* moeout = arena + OFF_MOE;
    float* rm     = arena + OFF_RM;
    float* rl     = arena + OFF_RL;

    float* out = (float*)d_out;
    float* outAttn = out + 4194304;

    dim3 T(256);

    // q = x @ Wq + bq          (4096x1024x1024)
    tgemm<<<dim3(8, 32, 1), T>>>(x, Wq, bq, q, 4096, 1024, 1024, 0, 0, 0, 0, 1, 1);
    // kv = x @ Wkv + bkv       (4096x2048x1024)
    tgemm<<<dim3(16, 32, 1), T>>>(x, Wkv, bkv, kvb, 4096, 2048, 1024, 0, 0, 0, 0, 1, 1);

    // attention
    att_pass1<<<dim3(16, 64), T>>>(q, kvb, tmp, rm, rl);
    att_pass2<<<dim3(16, 64), T>>>(kvb, tmp, rm, rl, attout);
    attn_tr<<<dim3(4, 1024, 4), T>>>(tmp, outAttn);

    // out-proj + residual LN
    tgemm<<<dim3(8, 32, 1), T>>>(attout, Wp, bp, proj, 4096, 1024, 1024, 0, 0, 0, 0, 1, 1);
    ln_res<<<4096, T>>>(proj, x, 1.0f, g1, b1, x1);

    // soft-MoE
    tgemm<<<dim3(8, 32, 1), T>>>(x1, phi, nullptr, logits, 4096, 1024, 1024, 0, 0, 0, 0, 1, 0);
    row_softmax<<<4096, T>>>(logits, comb);
    disp_softmax<<<dim3(16, 4), T>>>(logits, dispT);

    // slots[b] = dispT[b] @ x1[b]   (batched over b)
    tgemm<<<dim3(8, 8, 4), T>>>(dispT, x1, nullptr, slots, 1024, 1024, 1024,
                                1048576, 1048576, 0, 1048576, 0, 0);
    // h = gelu(slots @ We1[e] + be1[e])   (batched over (b,e), e = z % 2)
    tgemm<<<dim3(32, 4, 8), T>>>(slots, We1, be1, hbuf, 512, 4096, 1024,
                                 524288, 4194304, 4096, 2097152, 2, 2);
    // y = h @ We2[e] + be2[e]
    tgemm<<<dim3(8, 4, 8), T>>>(hbuf, We2, be2, ymoe, 512, 1024, 4096,
                                2097152, 4194304, 1024, 524288, 2, 1);
    // moe_out[b] = comb[b] @ ymoe[b]
    tgemm<<<dim3(8, 8, 4), T>>>(comb, ymoe, nullptr, moeout, 1024, 1024, 1024,
                                1048576, 1048576, 0, 1048576, 0, 0);

    // y = LN(moe_out + 2*x1)
    ln_res<<<4096, T>>>(moeout, x1, 2.0f, g2, b2, out);
}

// round 3
// speedup vs baseline: 3.0753x; 1.2024x over previous
#include <cuda_runtime.h>
#include <math.h>
#include <stdint.h>

// ---------------------------------------------------------------------------
// Problem constants
//   B=4, SEQ=1024, DIM=1024, HEADS=16, HD=64, N_EXP=2, SLOTS=512, HID=4096
// Output: [ y : 4*1024*1024 f32 ][ attn : 4*1024*1024*16 f32 ]
// ---------------------------------------------------------------------------

#define OFF_Q       0LL
#define OFF_KV      4194304LL
#define OFF_TMP     12582912LL     // attn raw-S scratch (b,h,n,m) 64M floats
#define OFF_ATTOUT  79691776LL
#define OFF_PROJ    83886080LL
#define OFF_X1      88080384LL
#define OFF_LOGITS  92274688LL
#define OFF_DISPT   96468992LL
#define OFF_COMB    100663296LL
#define OFF_SLOTS   104857600LL
#define OFF_H       109051904LL    // 16M floats
#define OFF_YMOE    125829120LL
#define OFF_MOE     130023424LL
#define OFF_RL      134283264LL
#define ARENA_FLOATS 134348800LL

__device__ float g_arena[ARENA_FLOATS];

__device__ __forceinline__ float gelu_tanh(float v) {
    const float c0 = 0.7978845608028654f;   // sqrt(2/pi)
    float t = tanhf(c0 * (v + 0.044715f * v * v * v));
    return 0.5f * v * (1.0f + t);
}

__device__ __forceinline__ float to_tf32(float x) {
    float r;
    asm("cvt.rna.tf32.f32 %0, %1;" : "=f"(r) : "f"(x));
    return r;
}

#define MMA_TF32(c0,c1,c2,c3,a0,a1,a2,a3,b0,b1)                               \
    asm volatile("mma.sync.aligned.m16n8k8.row.col.f32.tf32.tf32.f32 "        \
                 "{%0,%1,%2,%3},{%4,%5,%6,%7},{%8,%9},{%0,%1,%2,%3};"         \
                 : "+f"(c0), "+f"(c1), "+f"(c2), "+f"(c3)                     \
                 : "r"(a0), "r"(a1), "r"(a2), "r"(a3), "r"(b0), "r"(b1))

// ---------------------------------------------------------------------------
// tf32 tensor-core batched GEMM, double-buffered smem.
// C = A(MxK) @ B(KxN) [+bias] [gelu]; M,N mult of 128, K mult of 16.
// 256 threads = 8 warps (2x4), warp tile 64x32, mma m16n8k8.
// ---------------------------------------------------------------------------
__global__ void __launch_bounds__(256, 2)
tgemm(const float* __restrict__ A, const float* __restrict__ Bm,
      const float* __restrict__ bias, float* __restrict__ C,
      int M, int N, int K,
      long long sA, long long sB, long long sBias, long long sC,
      int nBmod, int act)
{
    int z = blockIdx.z;
    int zb = nBmod ? (z % nBmod) : z;
    A  += (long long)z * sA;
    Bm += (long long)zb * sB;
    if (act >= 1) bias += (long long)zb * sBias;
    C  += (long long)z * sC;

    __shared__ float As[2][128][20];   // [m][k16 pad 20]
    __shared__ float Bs[2][16][136];   // [k][n128 pad 136]

    int bx = blockIdx.x, by = blockIdx.y;
    int tid = threadIdx.x;
    int wid = tid >> 5;
    int lane = tid & 31;
    int g = lane >> 2;
    int j = lane & 3;
    int wm64 = (wid >> 2) * 64;
    int wn32 = (wid & 3) * 32;

    int aRow0 = tid >> 2;            // 0..63
    int aKc   = (tid & 3) * 4;       // 0,4,8,12
    int bRow0 = tid >> 5;            // 0..7
    int bCc   = (tid & 31) * 4;      // 0..124

    const float* Ap0 = A + (long long)(by * 128 + aRow0)      * K + aKc;
    const float* Ap1 = A + (long long)(by * 128 + aRow0 + 64) * K + aKc;
    const float* Bp0 = Bm + (long long)(bRow0)     * N + bx * 128 + bCc;
    const float* Bp1 = Bm + (long long)(bRow0 + 8) * N + bx * 128 + bCc;

    float c[4][4][4];
    #pragma unroll
    for (int mt = 0; mt < 4; mt++)
        #pragma unroll
        for (int nt = 0; nt < 4; nt++)
            #pragma unroll
            for (int r = 0; r < 4; r++) c[mt][nt][r] = 0.0f;

    float4 av0 = *(const float4*)Ap0;
    float4 av1 = *(const float4*)Ap1;
    float4 bv0 = *(const float4*)Bp0;
    float4 bv1 = *(const float4*)Bp1;

    // store tile 0
    {
        float4 t;
        t.x = to_tf32(av0.x); t.y = to_tf32(av0.y); t.z = to_tf32(av0.z); t.w = to_tf32(av0.w);
        *(float4*)&As[0][aRow0][aKc] = t;
        t.x = to_tf32(av1.x); t.y = to_tf32(av1.y); t.z = to_tf32(av1.z); t.w = to_tf32(av1.w);
        *(float4*)&As[0][aRow0 + 64][aKc] = t;
        t.x = to_tf32(bv0.x); t.y = to_tf32(bv0.y); t.z = to_tf32(bv0.z); t.w = to_tf32(bv0.w);
        *(float4*)&Bs[0][bRow0][bCc] = t;
        t.x = to_tf32(bv1.x); t.y = to_tf32(bv1.y); t.z = to_tf32(bv1.z); t.w = to_tf32(bv1.w);
        *(float4*)&Bs[0][bRow0 + 8][bCc] = t;
    }
    __syncthreads();

    int buf = 0;
    for (int k0 = 0; k0 < K; k0 += 16) {
        bool notlast = (k0 + 16 < K);
        if (notlast) {
            Ap0 += 16; Ap1 += 16;
            Bp0 += (long long)16 * N; Bp1 += (long long)16 * N;
            av0 = *(const float4*)Ap0;
            av1 = *(const float4*)Ap1;
            bv0 = *(const float4*)Bp0;
            bv1 = *(const float4*)Bp1;
        }
        #pragma unroll
        for (int kk = 0; kk < 16; kk += 8) {
            uint32_t a[4][4];
            uint32_t bfr[4][2];
            #pragma unroll
            for (int mt = 0; mt < 4; mt++) {
                const float* p = &As[buf][wm64 + mt * 16 + g][kk + j];
                a[mt][0] = __float_as_uint(p[0]);
                a[mt][1] = __float_as_uint(p[8 * 20]);
                a[mt][2] = __float_as_uint(p[4]);
                a[mt][3] = __float_as_uint(p[8 * 20 + 4]);
            }
            #pragma unroll
            for (int nt = 0; nt < 4; nt++) {
                const float* p = &Bs[buf][kk + j][wn32 + nt * 8 + g];
                bfr[nt][0] = __float_as_uint(p[0]);
                bfr[nt][1] = __float_as_uint(p[4 * 136]);
            }
            #pragma unroll
            for (int mt = 0; mt < 4; mt++)
                #pragma unroll
                for (int nt = 0; nt < 4; nt++)
                    MMA_TF32(c[mt][nt][0], c[mt][nt][1], c[mt][nt][2], c[mt][nt][3],
                             a[mt][0], a[mt][1], a[mt][2], a[mt][3],
                             bfr[nt][0], bfr[nt][1]);
        }
        if (notlast) {
            int nb = buf ^ 1;
            float4 t;
            t.x = to_tf32(av0.x); t.y = to_tf32(av0.y); t.z = to_tf32(av0.z); t.w = to_tf32(av0.w);
            *(float4*)&As[nb][aRow0][aKc] = t;
            t.x = to_tf32(av1.x); t.y = to_tf32(av1.y); t.z = to_tf32(av1.z); t.w = to_tf32(av1.w);
            *(float4*)&As[nb][aRow0 + 64][aKc] = t;
            t.x = to_tf32(bv0.x); t.y = to_tf32(bv0.y); t.z = to_tf32(bv0.z); t.w = to_tf32(bv0.w);
            *(float4*)&Bs[nb][bRow0][bCc] = t;
            t.x = to_tf32(bv1.x); t.y = to_tf32(bv1.y); t.z = to_tf32(bv1.z); t.w = to_tf32(bv1.w);
            *(float4*)&Bs[nb][bRow0 + 8][bCc] = t;
            __syncthreads();
            buf = nb;
        }
    }

    // epilogue
    #pragma unroll
    for (int mt = 0; mt < 4; mt++) {
        int r0 = by * 128 + wm64 + mt * 16 + g;
        #pragma unroll
        for (int nt = 0; nt < 4; nt++) {
            int col = bx * 128 + wn32 + nt * 8 + 2 * j;
            float b0 = 0.0f, b1 = 0.0f;
            if (act >= 1) { b0 = bias[col]; b1 = bias[col + 1]; }
            float v0 = c[mt][nt][0] + b0;
            float v1 = c[mt][nt][1] + b1;
            float v2 = c[mt][nt][2] + b0;
            float v3 = c[mt][nt][3] + b1;
            if (act == 2) {
                v0 = gelu_tanh(v0); v1 = gelu_tanh(v1);
                v2 = gelu_tanh(v2); v3 = gelu_tanh(v3);
            }
            *(float2*)(C + (long long)r0 * N + col)       = make_float2(v0, v1);
            *(float2*)(C + (long long)(r0 + 8) * N + col) = make_float2(v2, v3);
        }
    }
}

// ---------------------------------------------------------------------------
// Attention pass 1 (tensor cores): per (b,h), n-tile 64.
// S = (0.125*Q) K^T via tf32 mma; raw S -> tmp(b,h,n,m); per-row sum of exp.
// No max subtraction (|S| small; exact softmax identity).
// ---------------------------------------------------------------------------
__global__ void __launch_bounds__(256)
att1_tc(const float* __restrict__ q, const float* __restrict__ kv,
        float* __restrict__ tmp, float* __restrict__ rowrl)
{
    int bh = blockIdx.y;
    int b = bh >> 4, h = bh & 15;
    int n0 = blockIdx.x * 64;

    __shared__ float Qs[64][68];     // A: [n][d]
    __shared__ float Kt[64][68];     // B(col): [m][d]
    __shared__ float sumacc[4][64];

    int tid = threadIdx.x, lane = tid & 31, wid = tid >> 5;
    int g = lane >> 2, j = lane & 3;
    int wm32 = (wid >> 2) * 32;
    int wn16 = (wid & 3) * 16;

    sumacc[tid >> 6][tid & 63] = 0.0f;

    for (int i = tid; i < 1024; i += 256) {
        int r = i >> 4, c4 = (i & 15) * 4;
        float4 v = *(const float4*)(q + ((size_t)(b * 1024 + n0 + r) * 1024) + h * 64 + c4);
        float4 t;
        t.x = to_tf32(v.x * 0.125f); t.y = to_tf32(v.y * 0.125f);
        t.z = to_tf32(v.z * 0.125f); t.w = to_tf32(v.w * 0.125f);
        *(float4*)&Qs[r][c4] = t;
    }

    for (int m0 = 0; m0 < 1024; m0 += 64) {
        __syncthreads();
        for (int i = tid; i < 1024; i += 256) {
            int r = i >> 4, c4 = (i & 15) * 4;
            float4 v = *(const float4*)(kv + ((size_t)(b * 1024 + m0 + r) * 2048) + h * 64 + c4);
            float4 t;
            t.x = to_tf32(v.x); t.y = to_tf32(v.y);
            t.z = to_tf32(v.z); t.w = to_tf32(v.w);
            *(float4*)&Kt[r][c4] = t;
        }
        __syncthreads();

        float c[2][2][4];
        #pragma unroll
        for (int mt = 0; mt < 2; mt++)
            #pragma unroll
            for (int nt = 0; nt < 2; nt++)
                #pragma unroll
                for (int r = 0; r < 4; r++) c[mt][nt][r] = 0.0f;

        #pragma unroll
        for (int kk = 0; kk < 64; kk += 8) {
            uint32_t a[2][4], bf[2][2];
            #pragma unroll
            for (int mt = 0; mt < 2; mt++) {
                const float* p = &Qs[wm32 + mt * 16 + g][kk + j];
                a[mt][0] = __float_as_uint(p[0]);
                a[mt][1] = __float_as_uint(p[8 * 68]);
                a[mt][2] = __float_as_uint(p[4]);
                a[mt][3] = __float_as_uint(p[8 * 68 + 4]);
            }
            #pragma unroll
            for (int nt = 0; nt < 2; nt++) {
                const float* p = &Kt[wn16 + nt * 8 + g][kk + j];
                bf[nt][0] = __float_as_uint(p[0]);
                bf[nt][1] = __float_as_uint(p[4]);
            }
            #pragma unroll
            for (int mt = 0; mt < 2; mt++)
                #pragma unroll
                for (int nt = 0; nt < 2; nt++)
                    MMA_TF32(c[mt][nt][0], c[mt][nt][1], c[mt][nt][2], c[mt][nt][3],
                             a[mt][0], a[mt][1], a[mt][2], a[mt][3],
                             bf[nt][0], bf[nt][1]);
        }

        #pragma unroll
        for (int mt = 0; mt < 2; mt++) {
            int r1 = wm32 + mt * 16 + g;
            float eA = 0.0f, eB = 0.0f;
            #pragma unroll
            for (int nt = 0; nt < 2; nt++) {
                int col = wn16 + nt * 8 + 2 * j;
                float* base = tmp + ((size_t)bh * 1024 + n0 + r1) * 1024 + m0 + col;
                *(float2*)base            = make_float2(c[mt][nt][0], c[mt][nt][1]);
                *(float2*)(base + 8 * 1024) = make_float2(c[mt][nt][2], c[mt][nt][3]);
                eA += __expf(c[mt][nt][0]) + __expf(c[mt][nt][1]);
                eB += __expf(c[mt][nt][2]) + __expf(c[mt][nt][3]);
            }
            eA += __shfl_xor_sync(0xffffffffu, eA, 1);
            eA += __shfl_xor_sync(0xffffffffu, eA, 2);
            eB += __shfl_xor_sync(0xffffffffu, eB, 1);
            eB += __shfl_xor_sync(0xffffffffu, eB, 2);
            if (j == 0) {
                sumacc[wn16 >> 4][r1]     += eA;
                sumacc[wn16 >> 4][r1 + 8] += eB;
            }
        }
    }
    __syncthreads();
    if (tid < 64)
        rowrl[(size_t)bh * 1024 + n0 + tid] =
            1.0f / (sumacc[0][tid] + sumacc[1][tid] + sumacc[2][tid] + sumacc[3][tid]);
}

// ---------------------------------------------------------------------------
// Attention pass 2 (tensor cores): O = (exp(S) @ V) * rl. Reads raw S.
// ---------------------------------------------------------------------------
__global__ void __launch_bounds__(256)
att2_tc(const float* __restrict__ kv, const float* __restrict__ tmp,
        const float* __restrict__ rowrl, float* __restrict__ attout)
{
    int bh = blockIdx.y;
    int b = bh >> 4, h = bh & 15;
    int n0 = blockIdx.x * 64;

    __shared__ float Ps[64][68];     // A: [n][m-chunk]
    __shared__ float Vs[64][72];     // B: [m-chunk][d]
    __shared__ float rl_s[64];

    int tid = threadIdx.x, lane = tid & 31, wid = tid >> 5;
    int g = lane >> 2, j = lane & 3;
    int wm32 = (wid >> 2) * 32;
    int wn16 = (wid & 3) * 16;

    if (tid < 64) rl_s[tid] = rowrl[(size_t)bh * 1024 + n0 + tid];

    float o[2][2][4];
    #pragma unroll
    for (int mt = 0; mt < 2; mt++)
        #pragma unroll
        for (int nt = 0; nt < 2; nt++)
            #pragma unroll
            for (int r = 0; r < 4; r++) o[mt][nt][r] = 0.0f;

    for (int m0 = 0; m0 < 1024; m0 += 64) {
        __syncthreads();
        for (int i = tid; i < 1024; i += 256) {
            int r = i >> 4, c4 = (i & 15) * 4;
            float4 s = *(const float4*)(tmp + ((size_t)bh * 1024 + n0 + r) * 1024 + m0 + c4);
            float4 t;
            t.x = to_tf32(__expf(s.x)); t.y = to_tf32(__expf(s.y));
            t.z = to_tf32(__expf(s.z)); t.w = to_tf32(__expf(s.w));
            *(float4*)&Ps[r][c4] = t;
        }
        for (int i = tid; i < 1024; i += 256) {
            int r = i >> 4, c4 = (i & 15) * 4;
            float4 v = *(const float4*)(kv + ((size_t)(b * 1024 + m0 + r) * 2048) + 1024 + h * 64 + c4);
            float4 t;
            t.x = to_tf32(v.x); t.y = to_tf32(v.y);
            t.z = to_tf32(v.z); t.w = to_tf32(v.w);
            *(float4*)&Vs[r][c4] = t;
        }
        __syncthreads();

        #pragma unroll
        for (int kk = 0; kk < 64; kk += 8) {
            uint32_t a[2][4], bf[2][2];
            #pragma unroll
            for (int mt = 0; mt < 2; mt++) {
                const float* p = &Ps[wm32 + mt * 16 + g][kk + j];
                a[mt][0] = __float_as_uint(p[0]);
                a[mt][1] = __float_as_uint(p[8 * 68]);
                a[mt][2] = __float_as_uint(p[4]);
                a[mt][3] = __float_as_uint(p[8 * 68 + 4]);
            }
            #pragma unroll
            for (int nt = 0; nt < 2; nt++) {
                const float* p = &Vs[kk + j][wn16 + nt * 8 + g];
                bf[nt][0] = __float_as_uint(p[0]);
                bf[nt][1] = __float_as_uint(p[4 * 72]);
            }
            #pragma unroll
            for (int mt = 0; mt < 2; mt++)
                #pragma unroll
                for (int nt = 0; nt < 2; nt++)
                    MMA_TF32(o[mt][nt][0], o[mt][nt][1], o[mt][nt][2], o[mt][nt][3],
                             a[mt][0], a[mt][1], a[mt][2], a[mt][3],
                             bf[nt][0], bf[nt][1]);
        }
    }

    #pragma unroll
    for (int mt = 0; mt < 2; mt++) {
        int r1 = wm32 + mt * 16 + g;
        float rlA = rl_s[r1], rlB = rl_s[r1 + 8];
        #pragma unroll
        for (int nt = 0; nt < 2; nt++) {
            int col = wn16 + nt * 8 + 2 * j;
            float* base = attout + ((size_t)(b * 1024 + n0 + r1) * 1024) + h * 64 + col;
            *(float2*)base              = make_float2(o[mt][nt][0] * rlA, o[mt][nt][1] * rlA);
            *(float2*)(base + 8 * 1024) = make_float2(o[mt][nt][2] * rlB, o[mt][nt][3] * rlB);
        }
    }
}

// ---------------------------------------------------------------------------
// Normalize + transpose: out(b,n,m,h) = exp(S(b,h,n,m)) * rl(b,h,n).
// ---------------------------------------------------------------------------
__global__ void attn_tr(const float* __restrict__ tmp, const float* __restrict__ rowrl,
                        float* __restrict__ outAttn)
{
    int b = blockIdx.z;
    int n = blockIdx.y;
    int m0 = blockIdx.x * 256;
    __shared__ float T[16][257];
    __shared__ float rl_s[16];
    int tid = threadIdx.x;
    if (tid < 16) rl_s[tid] = rowrl[(size_t)(b * 16 + tid) * 1024 + n];
    __syncthreads();
    for (int i = tid; i < 16 * 256; i += 256) {
        int hh = i >> 8, mm = i & 255;
        T[hh][mm] = __expf(tmp[((size_t)(b * 16 + hh) * 1024 + n) * 1024 + m0 + mm]) * rl_s[hh];
    }
    __syncthreads();
    float* dst = outAttn + ((size_t)(b * 1024 + n) * 1024 + m0 + tid) * 16;
    #pragma unroll
    for (int k = 0; k < 16; k += 4) {
        *(float4*)(dst + k) = make_float4(T[k][tid], T[k + 1][tid], T[k + 2][tid], T[k + 3][tid]);
    }
}

// ---------------------------------------------------------------------------
// Row softmax over contiguous 1024 (combine weights).
// ---------------------------------------------------------------------------
__global__ void row_softmax(const float* __restrict__ in, float* __restrict__ outp)
{
    size_t row = blockIdx.x;
    const float4* L = (const float4*)(in + row * 1024);
    float4* O = (float4*)(outp + row * 1024);
    int t = threadIdx.x;
    float4 v = L[t];
    float mx = fmaxf(fmaxf(v.x, v.y), fmaxf(v.z, v.w));
    __shared__ float smA[8], smB[8];
    #pragma unroll
    for (int off = 16; off; off >>= 1) mx = fmaxf(mx, __shfl_xor_sync(0xffffffffu, mx, off));
    if ((t & 31) == 0) smA[t >> 5] = mx;
    __syncthreads();
    mx = smA[0];
    #pragma unroll
    for (int w = 1; w < 8; w++) mx = fmaxf(mx, smA[w]);
    float e0 = __expf(v.x - mx), e1 = __expf(v.y - mx);
    float e2 = __expf(v.z - mx), e3 = __expf(v.w - mx);
    float s = e0 + e1 + e2 + e3;
    #pragma unroll
    for (int off = 16; off; off >>= 1) s += __shfl_xor_sync(0xffffffffu, s, off);
    if ((t & 31) == 0) smB[t >> 5] = s;
    __syncthreads();
    s = 0.0f;
    #pragma unroll
    for (int w = 0; w < 8; w++) s += smB[w];
    float r = 1.0f / s;
    O[t] = make_float4(e0 * r, e1 * r, e2 * r, e3 * r);
}

// ---------------------------------------------------------------------------
// Dispatch softmax over token axis n, written TRANSPOSED: dispT[b][es][n].
// ---------------------------------------------------------------------------
__global__ void disp_softmax(const float* __restrict__ logits, float* __restrict__ dispT)
{
    int b = blockIdx.y;
    int c0 = blockIdx.x * 64;
    const float* L = logits + (size_t)b * 1048576;
    float* O = dispT + (size_t)b * 1048576;
    int tid = threadIdx.x;
    int tx = tid & 63, ty = tid >> 6;   // 4 x 64
    int col = c0 + tx;

    __shared__ float red[4][64];
    float mx = -1e30f;
    for (int n = ty; n < 1024; n += 4) mx = fmaxf(mx, L[(size_t)n * 1024 + col]);
    red[ty][tx] = mx;
    __syncthreads();
    mx = fmaxf(fmaxf(red[0][tx], red[1][tx]), fmaxf(red[2][tx], red[3][tx]));
    __syncthreads();
    float s = 0.0f;
    for (int n = ty; n < 1024; n += 4) s += __expf(L[(size_t)n * 1024 + col] - mx);
    red[ty][tx] = s;
    __syncthreads();
    s = red[0][tx] + red[1][tx] + red[2][tx] + red[3][tx];
    float rinv = 1.0f / s;
    __syncthreads();

    __shared__ float T[64][65];
    for (int n0 = 0; n0 < 1024; n0 += 64) {
        for (int n = ty; n < 64; n += 4)
            T[tx][n] = __expf(L[(size_t)(n0 + n) * 1024 + col] - mx) * rinv;
        __syncthreads();
        int cl = tid >> 2;
        int nl = (tid & 3) * 16;
        float* dst = O + (size_t)(c0 + cl) * 1024 + n0 + nl;
        #pragma unroll
        for (int k = 0; k < 16; k += 4)
            *(float4*)(dst + k) = make_float4(T[cl][nl + k], T[cl][nl + k + 1],
                                              T[cl][nl + k + 2], T[cl][nl + k + 3]);
        __syncthreads();
    }
}

// ---------------------------------------------------------------------------
// Fused residual + LayerNorm: out = LN(a + coefb * bsrc) * g + beta
// ---------------------------------------------------------------------------
__global__ void ln_res(const float* __restrict__ a, const float* __restrict__ bsrc,
                       float coefb, const float* __restrict__ g,
                       const float* __restrict__ beta, float* __restrict__ outp)
{
    size_t row = blockIdx.x;
    int t = threadIdx.x;
    float4 av = ((const float4*)(a + row * 1024))[t];
    float4 bv = ((const float4*)(bsrc + row * 1024))[t];
    float x0 = av.x + coefb * bv.x;
    float x1 = av.y + coefb * bv.y;
    float x2 = av.z + coefb * bv.z;
    float x3 = av.w + coefb * bv.w;
    float s = x0 + x1 + x2 + x3;
    float q = x0 * x0 + x1 * x1 + x2 * x2 + x3 * x3;
    __shared__ float smA[8], smB[8];
    #pragma unroll
    for (int off = 16; off; off >>= 1) {
        s += __shfl_xor_sync(0xffffffffu, s, off);
        q += __shfl_xor_sync(0xffffffffu, q, off);
    }
    if ((t & 31) == 0) { smA[t >> 5] = s; smB[t >> 5] = q; }
    __syncthreads();
    s = 0.0f; q = 0.0f;
    #pragma unroll
    for (int w = 0; w < 8; w++) { s += smA[w]; q += smB[w]; }
    float mu = s * (1.0f / 1024.0f);
    float var = q * (1.0f / 1024.0f) - mu * mu;
    float rs = rsqrtf(var + 1e-5f);
    float4 gv = ((const float4*)g)[t];
    float4 btv = ((const float4*)beta)[t];
    float4 out4;
    out4.x = (x0 - mu) * rs * gv.x + btv.x;
    out4.y = (x1 - mu) * rs * gv.y + btv.y;
    out4.z = (x2 - mu) * rs * gv.z + btv.z;
    out4.w = (x3 - mu) * rs * gv.w + btv.w;
    ((float4*)(outp + row * 1024))[t] = out4;
}

// ---------------------------------------------------------------------------
// Launcher
// ---------------------------------------------------------------------------
extern "C" void kernel_launch(void* const* d_in, const int* in_sizes, int n_in,
                              void* d_out, int out_size)
{
    const float* x   = (const float*)d_in[0];
    const float* Wq  = (const float*)d_in[1];
    const float* bq  = (const float*)d_in[2];
    const float* Wkv = (const float*)d_in[3];
    const float* bkv = (const float*)d_in[4];
    const float* Wp  = (const float*)d_in[5];
    const float* bp  = (const float*)d_in[6];
    const float* g1  = (const float*)d_in[7];
    const float* b1  = (const float*)d_in[8];
    const float* phi = (const float*)d_in[9];
    const float* We1 = (const float*)d_in[10];
    const float* be1 = (const float*)d_in[11];
    const float* We2 = (const float*)d_in[12];
    const float* be2 = (const float*)d_in[13];
    const float* g2  = (const float*)d_in[14];
    const float* b2  = (const float*)d_in[15];

    float* arena = nullptr;
    cudaGetSymbolAddress((void**)&arena, g_arena);

    float* q      = arena + OFF_Q;
    float* kvb    = arena + OFF_KV;
    float* tmp    = arena + OFF_TMP;
    float* attout = arena + OFF_ATTOUT;
    float* proj   = arena + OFF_PROJ;
    float* x1     = arena + OFF_X1;
    float* logits = arena + OFF_LOGITS;
    float* dispT  = arena + OFF_DISPT;
    float* comb   = arena + OFF_COMB;
    float* slots  = arena + OFF_SLOTS;
    float* hbuf   = arena + OFF_H;
    float* ymoe   = arena + OFF_YMOE;
    float* moeout = arena + OFF_MOE;
    float* rl     = arena + OFF_RL;

    float* out = (float*)d_out;
    float* outAttn = out + 4194304;

    dim3 T(256);

    // q = x @ Wq + bq          (4096x1024x1024)
    tgemm<<<dim3(8, 32, 1), T>>>(x, Wq, bq, q, 4096, 1024, 1024, 0, 0, 0, 0, 1, 1);
    // kv = x @ Wkv + bkv       (4096x2048x1024)
    tgemm<<<dim3(16, 32, 1), T>>>(x, Wkv, bkv, kvb, 4096, 2048, 1024, 0, 0, 0, 0, 1, 1);

    // attention (tensor cores, no-max softmax)
    att1_tc<<<dim3(16, 64), T>>>(q, kvb, tmp, rl);
    att2_tc<<<dim3(16, 64), T>>>(kvb, tmp, rl, attout);
    attn_tr<<<dim3(4, 1024, 4), T>>>(tmp, rl, outAttn);

    // out-proj + residual LN
    tgemm<<<dim3(8, 32, 1), T>>>(attout, Wp, bp, proj, 4096, 1024, 1024, 0, 0, 0, 0, 1, 1);
    ln_res<<<4096, T>>>(proj, x, 1.0f, g1, b1, x1);

    // soft-MoE
    tgemm<<<dim3(8, 32, 1), T>>>(x1, phi, nullptr, logits, 4096, 1024, 1024, 0, 0, 0, 0, 1, 0);
    row_softmax<<<4096, T>>>(logits, comb);
    disp_softmax<<<dim3(16, 4), T>>>(logits, dispT);

    // slots[b] = dispT[b] @ x1[b]
    tgemm<<<dim3(8, 8, 4), T>>>(dispT, x1, nullptr, slots, 1024, 1024, 1024,
                                1048576, 1048576, 0, 1048576, 0, 0);
    // h = gelu(slots @ We1[e] + be1[e])
    tgemm<<<dim3(32, 4, 8), T>>>(slots, We1, be1, hbuf, 512, 4096, 1024,
                                 524288, 4194304, 4096, 2097152, 2, 2);
    // y = h @ We2[e] + be2[e]
    tgemm<<<dim3(8, 4, 8), T>>>(hbuf, We2, be2, ymoe, 512, 1024, 4096,
                                2097152, 4194304, 1024, 524288, 2, 1);
    // moe_out[b] = comb[b] @ ymoe[b]
    tgemm<<<dim3(8, 8, 4), T>>>(comb, ymoe, nullptr, moeout, 1024, 1024, 1024,
                                1048576, 1048576, 0, 1048576, 0, 0);

    // y = LN(moe_out + 2*x1)
    ln_res<<<4096, T>>>(moeout, x1, 2.0f, g2, b2, out);
}